// round 9
// baseline (speedup 1.0000x reference)
#include <cuda_runtime.h>
#include <cstddef>

// GraphSage gather + cosine top-16 + mean.  (Round 9 = R8 with fixed PTX)
//   d_in[0] nodes  : int32 [N]
//   d_in[1] neigh  : int32 [N, 32]
//   d_in[2] u2e_visual : f32 [500000, 64]
//   d_in[3] u2e_text   : f32 [500000, 64]
// Output: f32 concat(u_v, u_t, v_agg, t_agg), each [N, 64].
//
// R3 structure (proven best): one warp per (node, modality), modality-major
// order, 8-lane-group sim loop with independent butterflies, rank-count
// top-16, 16-lane mean loop. Deltas vs R3:
//  * embedding-row loads carry an L2::evict_last cache policy (via
//    createpolicy + ld.global.nc.L2::cache_hint) — per-phase table (~128 MB)
//    ~fits L2 (~126 MB); sticky table lines + evict-first outputs/indices
//    target the ~150 MB of L2 capacity misses.
//  * group g owns neighbors 8g..8g+7: sim lands on lane L directly
//    (no redistribute shfl, single fdividef per lane).

#define DEG   32
#define TOPK  16
#define EMB   64

__device__ __forceinline__ unsigned long long mk_policy() {
    unsigned long long pol;
    asm("createpolicy.fractional.L2::evict_last.b64 %0, 1.0;" : "=l"(pol));
    return pol;
}

__device__ __forceinline__ float4 ldg_el(const float4* p, unsigned long long pol) {
    float4 v;
    asm("ld.global.nc.L2::cache_hint.v4.f32 {%0,%1,%2,%3}, [%4], %5;"
        : "=f"(v.x), "=f"(v.y), "=f"(v.z), "=f"(v.w) : "l"(p), "l"(pol));
    return v;
}

__global__ __launch_bounds__(256, 7) void gs_kernel(
    const int*   __restrict__ nodes,
    const int*   __restrict__ neigh,
    const float* __restrict__ uv,
    const float* __restrict__ ut,
    float*       __restrict__ out,
    int n)
{
    const unsigned FULL = 0xffffffffu;
    int wg = (int)((blockIdx.x * blockDim.x + threadIdx.x) >> 5);
    if (wg >= 2 * n) return;
    int lane = threadIdx.x & 31;

    // modality-major task order: [0,n) = visual, [n,2n) = text
    int m    = (wg >= n) ? 1 : 0;
    int node = wg - m * n;
    const float* __restrict__ emb = m ? ut : uv;

    unsigned long long pol = mk_policy();

    int g = lane >> 3;     // 8-lane group id (0..3): owns neighbors 8g..8g+7
    int s = lane & 7;      // sub-lane within group

    // ---- center gather (lane s holds float4 s and s+8 of the row) ----
    int cidx = __ldcs(nodes + node);
    const float4* crow = (const float4*)(emb + (size_t)cidx * EMB);
    float4 ua = ldg_el(crow + s, pol);
    float4 ub = ldg_el(crow + s + 8, pol);

    size_t nn = (size_t)n * EMB;
    float4* cout = (float4*)(out + (size_t)m * nn + (size_t)node * EMB);
    if (g == 0) { __stcs(cout + s, ua); __stcs(cout + s + 8, ub); }

    // ---- neighbor indices: lane k holds neigh[node][k] ----
    int nidx = __ldcs(neigh + (size_t)node * DEG + lane);

    // ---- rank value per neighbor: dot*|dot|/||v||^2 (strictly monotone in
    //      cosine; center norm is a positive per-node constant) ----
    float fd = 0.0f, fn = 1.0f;
    #pragma unroll
    for (int t = 0; t < 8; t++) {
        int j = __shfl_sync(FULL, nidx, 8 * g + t);
        const float4* vrow = (const float4*)(emb + (size_t)j * EMB);
        float4 va = ldg_el(vrow + s, pol);
        float4 vb = ldg_el(vrow + s + 8, pol);
        float dot = va.x * ua.x + va.y * ua.y + va.z * ua.z + va.w * ua.w
                  + vb.x * ub.x + vb.y * ub.y + vb.z * ub.z + vb.w * ub.w;
        float nsq = va.x * va.x + va.y * va.y + va.z * va.z + va.w * va.w
                  + vb.x * vb.x + vb.y * vb.y + vb.z * vb.z + vb.w * vb.w;
        #pragma unroll
        for (int d = 1; d < 8; d <<= 1) {        // independent 3-step butterflies
            dot += __shfl_xor_sync(FULL, dot, d);
            nsq += __shfl_xor_sync(FULL, nsq, d);
        }
        if (s == t) { fd = dot; fn = nsq; }      // lane 8g+t keeps neighbor 8g+t
    }
    float mysim = __fdividef(fd * fabsf(fd), fn + 1e-20f);

    // ---- stable top-16 via rank count (matches jax.lax.top_k tie-break) ----
    int cnt = 0;
    #pragma unroll
    for (int d = 1; d < DEG; d++) {
        float o = __shfl_xor_sync(FULL, mysim, d);
        int jl = lane ^ d;
        cnt += (o > mysim) || (o == mysim && jl < lane);
    }
    unsigned sel = __ballot_sync(FULL, cnt < TOPK);   // exactly TOPK bits set

    // ---- mean of selected (unnormalized) rows ----
    int half = lane >> 4;   // 16-lane halves: 2 neighbors per iteration
    int sub  = lane & 15;
    float4 acc = make_float4(0.f, 0.f, 0.f, 0.f);
    #pragma unroll
    for (int k = 0; k < DEG; k += 2) {
        int kk = k + half;
        int j = __shfl_sync(FULL, nidx, kk);
        if (sel & (1u << kk)) {
            float4 vv = ldg_el((const float4*)(emb + (size_t)j * EMB) + sub, pol);
            acc.x += vv.x; acc.y += vv.y; acc.z += vv.z; acc.w += vv.w;
        }
    }
    acc.x += __shfl_xor_sync(FULL, acc.x, 16);
    acc.y += __shfl_xor_sync(FULL, acc.y, 16);
    acc.z += __shfl_xor_sync(FULL, acc.z, 16);
    acc.w += __shfl_xor_sync(FULL, acc.w, 16);

    if (half == 0) {
        const float sc = 1.0f / (float)TOPK;
        float4 r = make_float4(acc.x * sc, acc.y * sc, acc.z * sc, acc.w * sc);
        float4* aout = (float4*)(out + (size_t)(2 + m) * nn + (size_t)node * EMB);
        __stcs(aout + sub, r);
    }
}

extern "C" void kernel_launch(void* const* d_in, const int* in_sizes, int n_in,
                              void* d_out, int out_size) {
    const int*   nodes = (const int*)d_in[0];
    const int*   neigh = (const int*)d_in[1];
    const float* uv    = (const float*)d_in[2];
    const float* ut    = (const float*)d_in[3];
    float*       out   = (float*)d_out;
    int n = in_sizes[0];
    int warps = 2 * n;
    int threads = 256;
    int blocks = (warps * 32 + threads - 1) / threads;
    gs_kernel<<<blocks, threads>>>(nodes, neigh, uv, ut, out, n);
}